// round 7
// baseline (speedup 1.0000x reference)
#include <cuda_runtime.h>
#include <cuda_bf16.h>
#include <cuda_fp8.h>
#include <cstdint>
#include <cstddef>

// ============================================================================
// Problem constants (shapes fixed by the dataset)
// ============================================================================
static constexpr int KDIM = 4096;   // inner dim
static constexpr int NDIM = 4096;   // out features
static constexpr int MMAX = 8192;   // 4*2048 rows

// bf16 scratch for quantized activations / weights (device globals: no alloc)
__device__ __align__(1024) __nv_bfloat16 g_xq[(size_t)MMAX * KDIM];
__device__ __align__(1024) __nv_bfloat16 g_wq[(size_t)NDIM * KDIM];

#define DINL static __device__ __forceinline__

DINL uint32_t smem_u32(const void* p) {
    uint32_t a;
    asm("{ .reg .u64 t; cvta.to.shared.u64 t, %1; cvt.u32.u64 %0, t; }"
        : "=r"(a) : "l"(p));
    return a;
}
DINL void cp16(uint32_t s, const void* g) {
    asm volatile("cp.async.cg.shared.global [%0], [%1], 16;" :: "r"(s), "l"(g));
}
DINL void cp_commit() { asm volatile("cp.async.commit_group;" ::: "memory"); }
DINL void cp_wait2()  { asm volatile("cp.async.wait_group 2;" ::: "memory"); }

DINL void mbar_init(uint32_t a, uint32_t cnt) {
    asm volatile("mbarrier.init.shared.b64 [%0], %1;" :: "r"(a), "r"(cnt) : "memory");
}
DINL void mbar_arrive(uint32_t a) {
    asm volatile("mbarrier.arrive.shared.b64 _, [%0];" :: "r"(a) : "memory");
}
DINL void mbar_wait(uint32_t a, uint32_t parity) {
    asm volatile(
        "{\n\t.reg .pred P;\n\t"
        "LAB_W_%=:\n\t"
        "mbarrier.try_wait.parity.acquire.cta.shared::cta.b64 P, [%0], %1, 0x989680;\n\t"
        "@P bra LAB_D_%=;\n\t"
        "bra LAB_W_%=;\n\t"
        "LAB_D_%=:\n\t}"
        :: "r"(a), "r"(parity) : "memory");
}

DINL void ldmx4(uint32_t* r, uint32_t addr) {
    asm volatile("ldmatrix.sync.aligned.m8n8.x4.shared.b16 {%0,%1,%2,%3}, [%4];"
                 : "=r"(r[0]), "=r"(r[1]), "=r"(r[2]), "=r"(r[3]) : "r"(addr));
}
DINL void mma_bf16(float* c, const uint32_t* a, const uint32_t* b) {
    asm volatile(
        "mma.sync.aligned.m16n8k16.row.col.f32.bf16.bf16.f32 "
        "{%0,%1,%2,%3}, {%4,%5,%6,%7}, {%8,%9}, {%0,%1,%2,%3};"
        : "+f"(c[0]), "+f"(c[1]), "+f"(c[2]), "+f"(c[3])
        : "r"(a[0]), "r"(a[1]), "r"(a[2]), "r"(a[3]), "r"(b[0]), "r"(b[1]));
}

// ============================================================================
// Kernel 1: fused RHT (sign diag + 16-pt Hadamard) + NVFP4 quant-dequant -> bf16
// One thread per 16-element block. Single launch covers x then weight.
// ============================================================================
__global__ void __launch_bounds__(256) quant_rht_kernel(
    const float* __restrict__ inx, const float* __restrict__ inw,
    const float* __restrict__ signs,
    __nv_bfloat16* __restrict__ outx, __nv_bfloat16* __restrict__ outw,
    int nblk_x, int nblk_tot)
{
    int b = blockIdx.x * blockDim.x + threadIdx.x;
    if (b >= nblk_tot) return;

    const float* in;
    __nv_bfloat16* out;
    int bb;
    if (b < nblk_x) { in = inx; out = outx; bb = b; }
    else            { in = inw; out = outw; bb = b - nblk_x; }

    float v[16];
    const float4* p = reinterpret_cast<const float4*>(in) + (size_t)bb * 4;
    const float4* sp = reinterpret_cast<const float4*>(signs);
#pragma unroll
    for (int i = 0; i < 4; i++) {
        float4 t = p[i];
        float4 s = sp[i];
        v[4 * i + 0] = t.x * s.x; v[4 * i + 1] = t.y * s.y;
        v[4 * i + 2] = t.z * s.z; v[4 * i + 3] = t.w * s.w;
    }

    // Sylvester FWHT (matches np.block([[H,H],[H,-H]]) doubling), then /sqrt(16)
#pragma unroll
    for (int h = 1; h < 16; h <<= 1) {
#pragma unroll
        for (int i = 0; i < 16; i++) {
            if ((i & h) == 0) {
                float a = v[i], c = v[i + h];
                v[i] = a + c; v[i + h] = a - c;
            }
        }
    }
    float amax = 0.f;
#pragma unroll
    for (int i = 0; i < 16; i++) { v[i] *= 0.25f; amax = fmaxf(amax, fabsf(v[i])); }

    // E4M3 block scale, exactly like reference: rn-to-e4m3(amax/6)
    float scale = (float)__nv_fp8_e4m3(__fdiv_rn(amax, 6.0f));

    __nv_bfloat16 o[16];
    if (scale == 0.0f) {
#pragma unroll
        for (int i = 0; i < 16; i++) o[i] = __float2bfloat16_rn(0.0f);
    } else {
        // thresholds mid*scale: |v| > mid*scale  <=>  rn(|v|/scale) > mid
        const float t0 = 0.25f * scale, t1 = 0.75f * scale, t2 = 1.25f * scale,
                    t3 = 1.75f * scale, t4 = 2.5f * scale,  t5 = 3.5f * scale,
                    t6 = 5.0f * scale;
#pragma unroll
        for (int i = 0; i < 16; i++) {
            float av = fabsf(v[i]);
            float q = 0.0f;
            q = (av > t0) ? 0.5f : q;
            q = (av > t1) ? 1.0f : q;
            q = (av > t2) ? 1.5f : q;
            q = (av > t3) ? 2.0f : q;
            q = (av > t4) ? 3.0f : q;
            q = (av > t5) ? 4.0f : q;
            q = (av > t6) ? 6.0f : q;
            o[i] = __float2bfloat16_rn(copysignf(q * scale, v[i]));  // exact in bf16
        }
    }

    uint32_t w[8];
#pragma unroll
    for (int i = 0; i < 8; i++) {
        __nv_bfloat162 t = __halves2bfloat162(o[2 * i], o[2 * i + 1]);
        w[i] = *reinterpret_cast<uint32_t*>(&t);
    }
    uint4* dst = reinterpret_cast<uint4*>(out) + (size_t)bb * 2;
    dst[0] = make_uint4(w[0], w[1], w[2], w[3]);
    dst[1] = make_uint4(w[4], w[5], w[6], w[7]);
}

// ============================================================================
// Kernel 2: bf16 mma.sync GEMM  out[M,N] = A[M,K] * B[N,K]^T + bias
// BM=128, BN=256, BK=64 (128B rows), 4-stage cp.async pipeline, XOR-16B swizzle.
// 16 warps: 4(M) x 4(N); warp tile 32x64 (2 m-tiles x 8 n-tiles of m16n8k16).
// Mainloop synchronization via per-stage full/empty mbarriers (no __syncthreads):
// warps decouple instead of convoying at stage boundaries.
// ============================================================================
static constexpr int BM = 128, BN = 256, BK = 64, NST = 4;
static constexpr int NTHREADS = 512;
static constexpr uint32_t A_BYTES = BM * 128;               // 16 KB
static constexpr uint32_t B_BYTES = BN * 128;               // 32 KB
static constexpr uint32_t STAGE_BYTES = A_BYTES + B_BYTES;  // 48 KB
static constexpr uint32_t OFF_FULL  = 0;                    // 4 x 8B
static constexpr uint32_t OFF_EMPTY = 64;                   // 4 x 8B
static constexpr uint32_t OFF_BIAS  = 128;                  // 256 floats -> ends 1152
static constexpr uint32_t OFF_STAGE = 2048;
static constexpr uint32_t SMEM_DYN  = OFF_STAGE + NST * STAGE_BYTES;  // 198656

__global__ void __launch_bounds__(NTHREADS, 1) gemm_bf16_kernel(
    const __nv_bfloat16* __restrict__ A,   // [M, K] bf16
    const __nv_bfloat16* __restrict__ B,   // [N, K] bf16
    const float* __restrict__ bias,
    float* __restrict__ out, int m_tiles)
{
    extern __shared__ __align__(128) char smem[];
    const uint32_t sbase = smem_u32(smem);
    float* sbias = reinterpret_cast<float*>(smem + OFF_BIAS);

    const int tid = threadIdx.x;
    const int wid = tid >> 5, lane = tid & 31;
    const int wm = wid >> 2, wn = wid & 3;   // 4 x 4 warps, warp tile 32x64

    // CTA rasterization: supertiles of 16 mt x 16 nt (256 CTAs) for L2 reuse
    int bid = blockIdx.x;
    int mt_idx, nt_idx;
    if ((m_tiles & 15) == 0) {
        int s = bid >> 8, r = bid & 255;
        mt_idx = (s << 4) | (r & 15);
        nt_idx = r >> 4;
    } else {
        mt_idx = bid % m_tiles;
        nt_idx = bid / m_tiles;
    }
    const int m0 = mt_idx * BM, n0 = nt_idx * BN;

    if (tid == 0) {
#pragma unroll
        for (int s = 0; s < NST; s++) {
            mbar_init(sbase + OFF_FULL  + 8 * s, 16);
            mbar_init(sbase + OFF_EMPTY + 8 * s, 16);
        }
    }
    // bias -> smem
    if (tid < BN) sbias[tid] = bias[n0 + tid];

    // ---- cp.async fill (A: 2 rows/thread, B: 4 rows/thread, 16B each) ----
    const int frow = tid >> 3;        // 0..63
    const int fcu  = tid & 7;         // 16B unit 0..7
    const __nv_bfloat16* gA0 = A + (size_t)(m0 + frow) * KDIM + fcu * 8;
    const __nv_bfloat16* gB0 = B + (size_t)(n0 + frow) * KDIM + fcu * 8;

    auto fill_stage = [&](int stage, int kc) {
        uint32_t sa = sbase + OFF_STAGE + stage * STAGE_BYTES;
        uint32_t sb = sa + A_BYTES;
        const __nv_bfloat16* ga = gA0 + kc * BK;
        const __nv_bfloat16* gb = gB0 + kc * BK;
#pragma unroll
        for (int p = 0; p < 2; p++) {
            int r = frow + p * 64;
            uint32_t soff = r * 128 + ((fcu ^ (r & 7)) << 4);
            cp16(sa + soff, ga + (size_t)(p * 64) * KDIM);
        }
#pragma unroll
        for (int p = 0; p < 4; p++) {
            int r = frow + p * 64;
            uint32_t soff = r * 128 + ((fcu ^ (r & 7)) << 4);
            cp16(sb + soff, gb + (size_t)(p * 64) * KDIM);
        }
    };

    __syncthreads();   // mbarrier init + sbias visible before mainloop

    const int KCH = KDIM / BK;   // 64
    fill_stage(0, 0); cp_commit();
    fill_stage(1, 1); cp_commit();
    fill_stage(2, 2); cp_commit();

    float c[2][8][4];
#pragma unroll
    for (int i = 0; i < 2; i++)
#pragma unroll
        for (int j = 0; j < 8; j++)
#pragma unroll
            for (int k = 0; k < 4; k++) c[i][j][k] = 0.f;

    // ldmatrix lane address components
    const int a_r_in16 = lane & 15;
    const int a_uoff   = lane >> 4;          // 0 or 1
    const int b_r_in16 = (lane & 7) + ((lane >> 4) << 3);
    const int b_uoff   = (lane >> 3) & 1;

#pragma unroll 1
    for (int it = 0; it < KCH; it++) {
        const int cs = it & 3;
        const int fc = it + 3;
        if (fc < KCH) {
            const int f = fc & 3, n = fc >> 2;
            if (n >= 1) mbar_wait(sbase + OFF_EMPTY + 8 * f, (uint32_t)((n - 1) & 1));
            fill_stage(f, fc);
        }
        cp_commit();   // always commit (empty groups at tail keep accounting right)

        // own lanes' copies for chunk `it` complete -> warp-arrive on full[cs]
        cp_wait2();
        __syncwarp();
        if (lane == 0) mbar_arrive(sbase + OFF_FULL + 8 * cs);
        // wait until all 16 warps' copies have landed
        mbar_wait(sbase + OFF_FULL + 8 * cs, (uint32_t)((it >> 2) & 1));

        uint32_t sa = sbase + OFF_STAGE + cs * STAGE_BYTES;
        uint32_t sb = sa + A_BYTES;

#pragma unroll
        for (int ks = 0; ks < 4; ks++) {
            uint32_t a[2][4], b2[4][4];
            // A fragments: 2 m-tiles of 16x16
#pragma unroll
            for (int mt = 0; mt < 2; mt++) {
                int r = wm * 32 + mt * 16 + a_r_in16;
                int u = ks * 2 + a_uoff;
                ldmx4(a[mt], sa + r * 128 + ((u ^ (r & 7)) << 4));
            }
            // B fragments: 4 x ldmatrix.x4, each covers two n-tiles (16 rows)
#pragma unroll
            for (int nh = 0; nh < 4; nh++) {
                int r = wn * 64 + nh * 16 + b_r_in16;
                int u = ks * 2 + b_uoff;
                ldmx4(b2[nh], sb + r * 128 + ((u ^ (r & 7)) << 4));
            }
#pragma unroll
            for (int mt = 0; mt < 2; mt++) {
#pragma unroll
                for (int nt = 0; nt < 8; nt++) {
                    const uint32_t bb[2] = { b2[nt >> 1][(nt & 1) * 2],
                                             b2[nt >> 1][(nt & 1) * 2 + 1] };
                    mma_bf16(c[mt][nt], a[mt], bb);
                }
            }
        }
        // all LDSM results consumed by MMA issue -> smem reads of stage cs retired
        __syncwarp();
        if (lane == 0) mbar_arrive(sbase + OFF_EMPTY + 8 * cs);
    }

    // ---- epilogue: direct float2 stores with bias ----
    const int er = lane >> 2;            // 0..7
    const int ec = (lane & 3) * 2;       // 0,2,4,6
#pragma unroll
    for (int mt = 0; mt < 2; mt++) {
        int row0 = m0 + wm * 32 + mt * 16 + er;
#pragma unroll
        for (int nt = 0; nt < 8; nt++) {
            int colL = wn * 64 + nt * 8 + ec;       // local col in [0,256)
            int col  = n0 + colL;
            float b0 = sbias[colL], b1 = sbias[colL + 1];
            float2 v0 = make_float2(c[mt][nt][0] + b0, c[mt][nt][1] + b1);
            float2 v1 = make_float2(c[mt][nt][2] + b0, c[mt][nt][3] + b1);
            *reinterpret_cast<float2*>(out + (size_t)row0 * NDIM + col) = v0;
            *reinterpret_cast<float2*>(out + (size_t)(row0 + 8) * NDIM + col) = v1;
        }
    }
}

// ============================================================================
// Host side
// ============================================================================
extern "C" void kernel_launch(void* const* d_in, const int* in_sizes, int n_in,
                              void* d_out, int out_size)
{
    const float* x        = (const float*)d_in[0];
    const float* weight   = (const float*)d_in[1];
    const float* bias     = (const float*)d_in[2];
    const float* signs_in = (const float*)d_in[3];
    // d_in[4] = signs_grad: unused in forward

    const int K = KDIM, N = NDIM;
    const int M = in_sizes[0] / K;

    __nv_bfloat16 *xq = nullptr, *wq = nullptr;
    cudaGetSymbolAddress((void**)&xq, g_xq);
    cudaGetSymbolAddress((void**)&wq, g_wq);

    // --- quantize x and weight to bf16 scratch (single launch) ---
    int nblk_x = M * (K / 16);
    int nblk_w = N * (K / 16);
    int nblk_tot = nblk_x + nblk_w;
    quant_rht_kernel<<<(nblk_tot + 255) / 256, 256>>>(
        x, weight, signs_in, xq, wq, nblk_x, nblk_tot);

    // --- GEMM ---
    static bool attr_set = false;
    if (!attr_set) {
        cudaFuncSetAttribute(gemm_bf16_kernel,
                             cudaFuncAttributeMaxDynamicSharedMemorySize, SMEM_DYN);
        attr_set = true;
    }
    int m_tiles = M / BM;            // 64
    int n_tiles = N / BN;            // 16
    gemm_bf16_kernel<<<m_tiles * n_tiles, NTHREADS, SMEM_DYN>>>(
        xq, wq, bias, (float*)d_out, m_tiles);
}

// round 8
// speedup vs baseline: 1.0691x; 1.0691x over previous
#include <cuda_runtime.h>
#include <cuda_bf16.h>
#include <cuda_fp8.h>
#include <cstdint>
#include <cstddef>

// ============================================================================
// Problem constants (shapes fixed by the dataset)
// ============================================================================
static constexpr int KDIM = 4096;   // inner dim
static constexpr int NDIM = 4096;   // out features
static constexpr int MMAX = 8192;   // 4*2048 rows

// bf16 scratch for quantized activations / weights (device globals: no alloc)
__device__ __align__(1024) __nv_bfloat16 g_xq[(size_t)MMAX * KDIM];
__device__ __align__(1024) __nv_bfloat16 g_wq[(size_t)NDIM * KDIM];

#define DINL static __device__ __forceinline__

DINL uint32_t smem_u32(const void* p) {
    uint32_t a;
    asm("{ .reg .u64 t; cvta.to.shared.u64 t, %1; cvt.u32.u64 %0, t; }"
        : "=r"(a) : "l"(p));
    return a;
}
DINL void cp16(uint32_t s, const void* g) {
    asm volatile("cp.async.cg.shared.global [%0], [%1], 16;" :: "r"(s), "l"(g));
}
DINL void cp_commit() { asm volatile("cp.async.commit_group;" ::: "memory"); }
DINL void cp_wait1()  { asm volatile("cp.async.wait_group 1;" ::: "memory"); }

DINL void ldmx4(uint32_t* r, uint32_t addr) {
    asm volatile("ldmatrix.sync.aligned.m8n8.x4.shared.b16 {%0,%1,%2,%3}, [%4];"
                 : "=r"(r[0]), "=r"(r[1]), "=r"(r[2]), "=r"(r[3]) : "r"(addr));
}
DINL void mma_bf16(float* c, const uint32_t* a, const uint32_t* b) {
    asm volatile(
        "mma.sync.aligned.m16n8k16.row.col.f32.bf16.bf16.f32 "
        "{%0,%1,%2,%3}, {%4,%5,%6,%7}, {%8,%9}, {%0,%1,%2,%3};"
        : "+f"(c[0]), "+f"(c[1]), "+f"(c[2]), "+f"(c[3])
        : "r"(a[0]), "r"(a[1]), "r"(a[2]), "r"(a[3]), "r"(b[0]), "r"(b[1]));
}

// ============================================================================
// Kernel 1: fused RHT (sign diag + 16-pt Hadamard) + NVFP4 quant-dequant -> bf16
// One thread per 16-element block. Single launch covers x then weight.
// ============================================================================
__global__ void __launch_bounds__(256) quant_rht_kernel(
    const float* __restrict__ inx, const float* __restrict__ inw,
    const float* __restrict__ signs,
    __nv_bfloat16* __restrict__ outx, __nv_bfloat16* __restrict__ outw,
    int nblk_x, int nblk_tot)
{
    int b = blockIdx.x * blockDim.x + threadIdx.x;
    if (b >= nblk_tot) return;

    const float* in;
    __nv_bfloat16* out;
    int bb;
    if (b < nblk_x) { in = inx; out = outx; bb = b; }
    else            { in = inw; out = outw; bb = b - nblk_x; }

    float v[16];
    const float4* p = reinterpret_cast<const float4*>(in) + (size_t)bb * 4;
    const float4* sp = reinterpret_cast<const float4*>(signs);
#pragma unroll
    for (int i = 0; i < 4; i++) {
        float4 t = p[i];
        float4 s = sp[i];
        v[4 * i + 0] = t.x * s.x; v[4 * i + 1] = t.y * s.y;
        v[4 * i + 2] = t.z * s.z; v[4 * i + 3] = t.w * s.w;
    }

    // Sylvester FWHT (matches np.block([[H,H],[H,-H]]) doubling), then /sqrt(16)
#pragma unroll
    for (int h = 1; h < 16; h <<= 1) {
#pragma unroll
        for (int i = 0; i < 16; i++) {
            if ((i & h) == 0) {
                float a = v[i], c = v[i + h];
                v[i] = a + c; v[i + h] = a - c;
            }
        }
    }
    float amax = 0.f;
#pragma unroll
    for (int i = 0; i < 16; i++) { v[i] *= 0.25f; amax = fmaxf(amax, fabsf(v[i])); }

    // E4M3 block scale, exactly like reference: rn-to-e4m3(amax/6)
    float scale = (float)__nv_fp8_e4m3(__fdiv_rn(amax, 6.0f));

    __nv_bfloat16 o[16];
    if (scale == 0.0f) {
#pragma unroll
        for (int i = 0; i < 16; i++) o[i] = __float2bfloat16_rn(0.0f);
    } else {
        // thresholds mid*scale: |v| > mid*scale  <=>  rn(|v|/scale) > mid
        const float t0 = 0.25f * scale, t1 = 0.75f * scale, t2 = 1.25f * scale,
                    t3 = 1.75f * scale, t4 = 2.5f * scale,  t5 = 3.5f * scale,
                    t6 = 5.0f * scale;
#pragma unroll
        for (int i = 0; i < 16; i++) {
            float av = fabsf(v[i]);
            float q = 0.0f;
            q = (av > t0) ? 0.5f : q;
            q = (av > t1) ? 1.0f : q;
            q = (av > t2) ? 1.5f : q;
            q = (av > t3) ? 2.0f : q;
            q = (av > t4) ? 3.0f : q;
            q = (av > t5) ? 4.0f : q;
            q = (av > t6) ? 6.0f : q;
            o[i] = __float2bfloat16_rn(copysignf(q * scale, v[i]));  // exact in bf16
        }
    }

    uint32_t w[8];
#pragma unroll
    for (int i = 0; i < 8; i++) {
        __nv_bfloat162 t = __halves2bfloat162(o[2 * i], o[2 * i + 1]);
        w[i] = *reinterpret_cast<uint32_t*>(&t);
    }
    uint4* dst = reinterpret_cast<uint4*>(out) + (size_t)bb * 2;
    dst[0] = make_uint4(w[0], w[1], w[2], w[3]);
    dst[1] = make_uint4(w[4], w[5], w[6], w[7]);
}

// ============================================================================
// Kernel 2: bf16 mma.sync GEMM  out[M,N] = A[M,K] * B[N,K]^T + bias
// BM=BN=128, BK=64 (128B rows), 3-stage cp.async pipeline, XOR-16B swizzle.
// 8 warps: 2(M) x 4(N); warp tile 64x32. 2 CTAs per SM (occupancy 2): while one
// CTA convoys at its stage barrier, the other keeps the tensor pipe fed.
// ============================================================================
static constexpr int BM = 128, BN = 128, BK = 64, NST = 3;
static constexpr uint32_t TILE_BYTES = 128 * 128;           // 16 KB (128 rows x 128B)
static constexpr uint32_t STAGE_BYTES = 2 * TILE_BYTES;     // A + B
static constexpr uint32_t OFF_BIAS = NST * STAGE_BYTES;     // 98304
static constexpr uint32_t SMEM_DYN = OFF_BIAS + BN * 4;     // + 512 -> 98816

__global__ void __launch_bounds__(256, 2) gemm_bf16_kernel(
    const __nv_bfloat16* __restrict__ A,   // [M, K] bf16
    const __nv_bfloat16* __restrict__ B,   // [N, K] bf16
    const float* __restrict__ bias,
    float* __restrict__ out, int m_tiles)
{
    extern __shared__ __align__(128) char smem[];
    const uint32_t sbase = smem_u32(smem);
    float* sbias = reinterpret_cast<float*>(smem + OFF_BIAS);

    const int tid = threadIdx.x;
    const int wid = tid >> 5, lane = tid & 31;
    const int wm = wid >> 2, wn = wid & 3;   // 2 x 4 warps, warp tile 64x32

    // CTA rasterization: supertiles of 16 mt x 16 nt (256 CTAs) for L2 reuse
    int bid = blockIdx.x;
    int mt_idx, nt_idx;
    if ((m_tiles & 15) == 0) {
        int s = bid >> 8, r = bid & 255;          // m_tiles=64, n_tiles=32 -> s in 0..7
        mt_idx = ((s & 3) << 4) | (r & 15);
        nt_idx = ((s >> 2) << 4) | (r >> 4);
    } else {
        mt_idx = bid % m_tiles;
        nt_idx = bid / m_tiles;
    }
    const int m0 = mt_idx * BM, n0 = nt_idx * BN;

    // bias -> smem
    if (tid < BN) sbias[tid] = bias[n0 + tid];

    // ---- cp.async fill helper (each thread: 4 A rows + 4 B rows, 16B each) ----
    const int frow = tid >> 3;        // 0..31
    const int fcu  = tid & 7;         // 16B unit 0..7
    const __nv_bfloat16* gA0 = A + (size_t)(m0 + frow) * KDIM + fcu * 8;
    const __nv_bfloat16* gB0 = B + (size_t)(n0 + frow) * KDIM + fcu * 8;

    auto fill_stage = [&](int stage, int kc) {
        uint32_t sa = sbase + stage * STAGE_BYTES;
        uint32_t sb = sa + TILE_BYTES;
        const __nv_bfloat16* ga = gA0 + kc * BK;
        const __nv_bfloat16* gb = gB0 + kc * BK;
#pragma unroll
        for (int p = 0; p < 4; p++) {
            int r = frow + p * 32;
            uint32_t soff = r * 128 + ((fcu ^ (r & 7)) << 4);
            cp16(sa + soff, ga + (size_t)(p * 32) * KDIM);
            cp16(sb + soff, gb + (size_t)(p * 32) * KDIM);
        }
    };

    const int KCH = KDIM / BK;   // 64
    fill_stage(0, 0); cp_commit();
    fill_stage(1, 1); cp_commit();

    float c[4][4][4];
#pragma unroll
    for (int i = 0; i < 4; i++)
#pragma unroll
        for (int j = 0; j < 4; j++)
#pragma unroll
            for (int k = 0; k < 4; k++) c[i][j][k] = 0.f;

    // ldmatrix lane address components
    const int a_r_in16 = lane & 15;
    const int a_uoff   = lane >> 4;          // 0 or 1
    const int b_r_in16 = (lane & 7) + ((lane >> 4) << 3);
    const int b_uoff   = (lane >> 3) & 1;

#pragma unroll 1
    for (int it = 0; it < KCH; it++) {
        cp_wait1();
        __syncthreads();
        if (it + 2 < KCH) fill_stage((it + 2) % NST, it + 2);
        cp_commit();   // empty group near tail keeps wait_group accounting right

        uint32_t sa = sbase + (it % NST) * STAGE_BYTES;
        uint32_t sb = sa + TILE_BYTES;

#pragma unroll
        for (int ks = 0; ks < 4; ks++) {
            uint32_t a[4][4], b2[2][4];
            // A fragments: 4 m-tiles of 16x16
#pragma unroll
            for (int mt = 0; mt < 4; mt++) {
                int r = wm * 64 + mt * 16 + a_r_in16;
                int u = ks * 2 + a_uoff;
                ldmx4(a[mt], sa + r * 128 + ((u ^ (r & 7)) << 4));
            }
            // B fragments: 2 x ldmatrix.x4, each covers two n-tiles (16 rows)
#pragma unroll
            for (int nh = 0; nh < 2; nh++) {
                int r = wn * 32 + nh * 16 + b_r_in16;
                int u = ks * 2 + b_uoff;
                ldmx4(b2[nh], sb + r * 128 + ((u ^ (r & 7)) << 4));
            }
#pragma unroll
            for (int mt = 0; mt < 4; mt++) {
#pragma unroll
                for (int nt = 0; nt < 4; nt++) {
                    const uint32_t bb[2] = { b2[nt >> 1][(nt & 1) * 2],
                                             b2[nt >> 1][(nt & 1) * 2 + 1] };
                    mma_bf16(c[mt][nt], a[mt], bb);
                }
            }
        }
    }

    // ---- epilogue: direct float2 stores with bias ----
    const int er = lane >> 2;            // 0..7
    const int ec = (lane & 3) * 2;       // 0,2,4,6
#pragma unroll
    for (int mt = 0; mt < 4; mt++) {
        int row0 = m0 + wm * 64 + mt * 16 + er;
#pragma unroll
        for (int nt = 0; nt < 4; nt++) {
            int colL = wn * 32 + nt * 8 + ec;       // local col in [0,128)
            int col  = n0 + colL;
            float b0 = sbias[colL], b1 = sbias[colL + 1];
            float2 v0 = make_float2(c[mt][nt][0] + b0, c[mt][nt][1] + b1);
            float2 v1 = make_float2(c[mt][nt][2] + b0, c[mt][nt][3] + b1);
            *reinterpret_cast<float2*>(out + (size_t)row0 * NDIM + col) = v0;
            *reinterpret_cast<float2*>(out + (size_t)(row0 + 8) * NDIM + col) = v1;
        }
    }
}

// ============================================================================
// Host side
// ============================================================================
extern "C" void kernel_launch(void* const* d_in, const int* in_sizes, int n_in,
                              void* d_out, int out_size)
{
    const float* x        = (const float*)d_in[0];
    const float* weight   = (const float*)d_in[1];
    const float* bias     = (const float*)d_in[2];
    const float* signs_in = (const float*)d_in[3];
    // d_in[4] = signs_grad: unused in forward

    const int K = KDIM, N = NDIM;
    const int M = in_sizes[0] / K;

    __nv_bfloat16 *xq = nullptr, *wq = nullptr;
    cudaGetSymbolAddress((void**)&xq, g_xq);
    cudaGetSymbolAddress((void**)&wq, g_wq);

    // --- quantize x and weight to bf16 scratch (single launch) ---
    int nblk_x = M * (K / 16);
    int nblk_w = N * (K / 16);
    int nblk_tot = nblk_x + nblk_w;
    quant_rht_kernel<<<(nblk_tot + 255) / 256, 256>>>(
        x, weight, signs_in, xq, wq, nblk_x, nblk_tot);

    // --- GEMM ---
    static bool attr_set = false;
    if (!attr_set) {
        cudaFuncSetAttribute(gemm_bf16_kernel,
                             cudaFuncAttributeMaxDynamicSharedMemorySize, SMEM_DYN);
        attr_set = true;
    }
    int m_tiles = M / BM;            // 64
    int n_tiles = N / BN;            // 32
    gemm_bf16_kernel<<<m_tiles * n_tiles, 256, SMEM_DYN>>>(
        xq, wq, bias, (float*)d_out, m_tiles);
}